// round 10
// baseline (speedup 1.0000x reference)
#include <cuda_runtime.h>
#include <cuda_bf16.h>

// Fixed shapes
#define BB 8
#define CC 8
#define HH 512
#define WW 1024
#define HWSZ (HH * WW)

// Tiling: 32x8 threads, each thread owns 4 consecutive pixels
#define BX 32
#define BY 8
#define TW (BX * 4)        // 128 px
#define TH BY              // 8 px
#define NWARPS 8
#define NBLOCKS ((WW / TW) * (HH / TH) * BB)   // 4096

#define HROWS (TH + 4)     // 12
#define HU 34              // uints per halo row (136 bytes: cols gx0-4 .. gx0+131)
#define HTOT (HROWS * HU)  // 408 uints

__device__ double g_acc[BB][26];   // zeroed at module load; last block re-zeroes
__device__ unsigned g_ticket;

#define CP(v, p) ((p) == 0 ? (v).x : (p) == 1 ? (v).y : (p) == 2 ? (v).z : (v).w)

__global__ __launch_bounds__(256, 4) void loss_main_kernel(
    const float* __restrict__ pred, const int* __restrict__ target,
    float* __restrict__ out)
{
    __shared__ __align__(16) unsigned s_t[HTOT];        // packed byte labels
    __shared__ float s_red[17][65];                     // stride 65: conflict-free tail
    __shared__ unsigned s_cnt[2][NWARPS];
    __shared__ float s_fin[2];
    __shared__ int s_last;

    const int b   = blockIdx.z;
    const int gx0 = blockIdx.x * TW;
    const int gy0 = blockIdx.y * TH;
    const int tx  = threadIdx.x;
    const int ty  = threadIdx.y;
    const int tid = ty * BX + tx;

    // ---- pred loads FIRST: 8 independent LDG.128 in flight across the whole
    //      staging + sync + morphology phase (this ordering is load-bearing;
    //      R9 moved it later and regressed 9%) ----
    const int gy = gy0 + ty;
    const int gx = gx0 + tx * 4;
    const float* pb = pred + (size_t)b * CC * HWSZ + (size_t)gy * WW + gx;
    float4 X[CC];
#pragma unroll
    for (int c = 0; c < CC; c++) X[c] = __ldcs((const float4*)(pb + (size_t)c * HWSZ));

    // ---- stage target halo as packed bytes: int4 load + PRMT pack ----
    // uint j of halo row covers cols gx0-4+4j .. +3; OOB uint -> 0xFFFFFFFF
    // (0xFF loses signed-byte max and unsigned-byte min)
    {
        const int* tgt_b = target + b * HWSZ;
#pragma unroll
        for (int k = 0; k < 2; k++) {
            int idx = tid + k * 256;
            if (idx < HTOT) {
                int row = idx / HU;
                int j   = idx - row * HU;
                int gyy = gy0 + row - 2;
                int cb  = gx0 - 4 + 4 * j;
                unsigned u = 0xFFFFFFFFu;
                if (gyy >= 0 && gyy < HH && cb >= 0 && cb < WW) {
                    int4 w = *(const int4*)(tgt_b + gyy * WW + cb);   // 16B-aligned
                    unsigned lo = __byte_perm((unsigned)w.x, (unsigned)w.y, 0x4040);
                    unsigned hi = __byte_perm((unsigned)w.z, (unsigned)w.w, 0x4040);
                    u = __byte_perm(lo, hi, 0x5410);
                }
                s_t[idx] = u;
            }
        }
    }
    __syncthreads();

    // ---- SIMD byte morphology over 12-byte window (uints tx, tx+1, tx+2) ----
    unsigned d, t_packed;
    {
        const int u0 = ty * HU + tx;
        unsigned r1a = s_t[u0 + HU],     r1b = s_t[u0 + HU + 1],     r1c = s_t[u0 + HU + 2];
        unsigned r2a = s_t[u0 + 2*HU],   r2b = s_t[u0 + 2*HU + 1],   r2c = s_t[u0 + 2*HU + 2];
        unsigned r3a = s_t[u0 + 3*HU],   r3b = s_t[u0 + 3*HU + 1],   r3c = s_t[u0 + 3*HU + 2];
        unsigned c0  = s_t[u0 + 1];               // row y-2, center col
        unsigned c4  = s_t[u0 + 4*HU + 1];        // row y+2, center col

        unsigned xl = __vmaxs4(__vmaxs4(r1a, r2a), r3a);
        unsigned xm = __vmaxs4(__vmaxs4(r1b, r2b), r3b);
        unsigned xh = __vmaxs4(__vmaxs4(r1c, r2c), r3c);
        unsigned nl = __vminu4(__vminu4(r1a, r2a), r3a);
        unsigned nm = __vminu4(__vminu4(r1b, r2b), r3b);
        unsigned nh = __vminu4(__vminu4(r1c, r2c), r3c);

        unsigned mx = __vmaxs4(
            __vmaxs4(__byte_perm(xl, xm, 0x5432), __byte_perm(xl, xm, 0x6543)),
            __vmaxs4(xm,
            __vmaxs4(__byte_perm(xm, xh, 0x4321), __byte_perm(xm, xh, 0x5432))));
        unsigned mn = __vminu4(
            __vminu4(__byte_perm(nl, nm, 0x5432), __byte_perm(nl, nm, 0x6543)),
            __vminu4(nm,
            __vminu4(__byte_perm(nm, nh, 0x4321), __byte_perm(nm, nh, 0x5432))));

        mx = __vmaxs4(mx, __vmaxs4(c0, c4));
        mn = __vminu4(mn, __vminu4(c0, c4));

        t_packed = r2b;          // 4 target labels (center row, center uint)
        d = mx ^ mn;             // nonzero byte -> boundary pixel
    }

    float sump[CC], inter[CC];
    unsigned cntA = 0, cntB = 0;
#pragma unroll
    for (int c = 0; c < CC; c++) { sump[c] = 0.f; inter[c] = 0.f; }
    float cw_s = 0.f;            // merged: ce*(CE_W + BD_W*w) = ce*(1+2w), w in {1,10}

#pragma unroll
    for (int p = 0; p < 4; p++) {
        const unsigned tp = __byte_perm(t_packed, 0u, 0x4440u | p);
        const unsigned db = __byte_perm(d, 0u, 0x4440u | p);

        // exp WITHOUT max-subtraction: inputs N(0,1), |x| < ~6, no overflow
        float e[CC];
#pragma unroll
        for (int c = 0; c < CC; c++) e[c] = __expf(CP(X[c], p));
        float se = ((e[0] + e[1]) + (e[2] + e[3])) + ((e[4] + e[5]) + (e[6] + e[7]));
        float inv;
        asm("rcp.approx.f32 %0, %1;" : "=f"(inv) : "f"(se));

        // target logit via select chain; ce = log(se) - x_t
        float xt = CP(X[0], p);
#pragma unroll
        for (int c = 1; c < CC; c++) xt = (tp == (unsigned)c) ? CP(X[c], p) : xt;
        const float ce = __logf(se) - xt;

#pragma unroll
        for (int c = 0; c < CC; c++) {
            sump[c] = fmaf(e[c], inv, sump[c]);
            if (tp == (unsigned)c) inter[c] = fmaf(e[c], inv, inter[c]);  // predicated FFMA
        }

        cw_s = fmaf(db ? 21.0f : 3.0f, ce, cw_s);

        unsigned inc = 1u << ((tp & 3u) * 8);
        cntA += (tp < 4u) ? inc : 0u;
        cntB += (tp < 4u) ? 0u : inc;
    }

    // ---- block reduction: 2 shuffle levels (lanes 0-7 hold partials) ----
    const int lane = tid & 31;
    const int warp = tid >> 5;
    {
        float q[17];
#pragma unroll
        for (int c = 0; c < CC; c++) { q[c] = sump[c]; q[8 + c] = inter[c]; }
        q[16] = cw_s;
#pragma unroll
        for (int k = 0; k < 17; k++) {
            float v = q[k];
            v += __shfl_down_sync(0xFFFFFFFFu, v, 16);
            v += __shfl_down_sync(0xFFFFFFFFu, v, 8);
            if (lane < 8) s_red[k][warp * 8 + lane] = v;
        }
        unsigned ua = __reduce_add_sync(0xFFFFFFFFu, cntA);   // REDUX.SUM
        unsigned ub = __reduce_add_sync(0xFFFFFFFFu, cntB);
        if (lane == 0) { s_cnt[0][warp] = ua; s_cnt[1][warp] = ub; }
    }
    __syncthreads();

    if (tid < 17) {
        float s = 0.f;
#pragma unroll
        for (int w = 0; w < 64; w++) s += s_red[tid][w];
        int gi = (tid < 16) ? tid : 24;
        atomicAdd(&g_acc[b][gi], (double)s);
    }
    if (tid >= 32 && tid < 40) {
        int c = tid - 32;
        unsigned s = 0;
#pragma unroll
        for (int w = 0; w < NWARPS; w++)
            s += (s_cnt[c >> 2][w] >> ((c & 3) * 8)) & 0xFFu;
        atomicAdd(&g_acc[b][16 + c], (double)s);
    }

    // ---- last-block finalize ----
    __syncthreads();
    if (tid == 0) {
        __threadfence();
        unsigned r = atomicAdd(&g_ticket, 1u);
        s_last = (r == NBLOCKS - 1);
        s_fin[0] = 0.f; s_fin[1] = 0.f;
    }
    __syncthreads();
    if (!s_last) return;
    __threadfence();

    float dterm = 0.f;
    if (tid < BB * CC) {
        int bb = tid >> 3, cc = tid & 7;
        float it   = (float)g_acc[bb][8 + cc];
        float card = (float)(g_acc[bb][cc] + g_acc[bb][16 + cc]);
        dterm = (2.0f * it + 1e-6f) / (card + 1e-6f);
    }
#pragma unroll
    for (int off = 16; off > 0; off >>= 1)
        dterm += __shfl_down_sync(0xFFFFFFFFu, dterm, off);
    if (lane == 0 && warp < 2) atomicAdd(&s_fin[0], dterm);
    if (tid < BB) atomicAdd(&s_fin[1], (float)g_acc[tid][24]);
    __syncthreads();

    if (tid == 0) {
        const float N = (float)BB * HH * WW;
        float dice = 1.0f - s_fin[0] / (float)(BB * CC);
        out[0] = s_fin[1] / N + 3.0f * dice;
    }
    if (tid < BB * 26) ((double*)g_acc)[tid] = 0.0;
    if (tid == 0) g_ticket = 0u;
}

extern "C" void kernel_launch(void* const* d_in, const int* in_sizes, int n_in,
                              void* d_out, int out_size)
{
    const float* pred   = (const float*)d_in[0];
    const int*   target = (const int*)d_in[1];
    float* out = (float*)d_out;

    dim3 block(BX, BY, 1);
    dim3 grid(WW / TW, HH / TH, BB);
    loss_main_kernel<<<grid, block>>>(pred, target, out);
}

// round 11
// speedup vs baseline: 1.5012x; 1.5012x over previous
#include <cuda_runtime.h>
#include <cuda_bf16.h>

// Fixed shapes
#define BB 8
#define CC 8
#define HH 512
#define WW 1024
#define HWSZ (HH * WW)

// Tiling: 32x8 threads, each thread owns 4 consecutive pixels
#define BX 32
#define BY 8
#define TW (BX * 4)        // 128 px
#define TH BY              // 8 px
#define NWARPS 8
#define NBLOCKS ((WW / TW) * (HH / TH) * BB)   // 4096

#define HROWS (TH + 4)     // 12
#define HU 34              // uints per halo row (136 bytes: cols gx0-4 .. gx0+131)
#define HTOT (HROWS * HU)  // 408 uints

__device__ double g_acc[BB][26];   // zeroed at module load; last block re-zeroes
__device__ unsigned g_ticket;

#define CP(v, p) ((p) == 0 ? (v).x : (p) == 1 ? (v).y : (p) == 2 ? (v).z : (v).w)

__global__ __launch_bounds__(256, 4) void loss_main_kernel(
    const float* __restrict__ pred, const int* __restrict__ target,
    float* __restrict__ out)
{
    __shared__ __align__(16) unsigned s_t[HTOT];        // packed byte labels
    __shared__ float s_red[17][33];                     // padded (bank-conflict-free)
    __shared__ unsigned s_cnt[2][NWARPS];
    __shared__ float s_fin[2];
    __shared__ int s_last;

    const int b   = blockIdx.z;
    const int gx0 = blockIdx.x * TW;
    const int gy0 = blockIdx.y * TH;
    const int tx  = threadIdx.x;
    const int ty  = threadIdx.y;
    const int tid = ty * BX + tx;

    // ---- HOISTED pred loads: 8 independent LDG.128 first; consumed after
    //      staging + sync + morphology (covers DRAM latency) ----
    const int gy = gy0 + ty;
    const int gx = gx0 + tx * 4;
    const float* pb = pred + (size_t)b * CC * HWSZ + (size_t)gy * WW + gx;
    float4 X[CC];
#pragma unroll
    for (int c = 0; c < CC; c++) X[c] = __ldcs((const float4*)(pb + (size_t)c * HWSZ));

    // ---- stage target halo as packed bytes: int4 load + PRMT pack ----
    // uint j of halo row covers cols gx0-4+4j .. +3; OOB uint -> 0xFFFFFFFF
    // (0xFF loses signed-byte max and unsigned-byte min)
    {
        const int* tgt_b = target + b * HWSZ;
#pragma unroll
        for (int k = 0; k < 2; k++) {
            int idx = tid + k * 256;
            if (idx < HTOT) {
                int row = idx / HU;
                int j   = idx - row * HU;
                int gyy = gy0 + row - 2;
                int cb  = gx0 - 4 + 4 * j;
                unsigned u = 0xFFFFFFFFu;
                if (gyy >= 0 && gyy < HH && cb >= 0 && cb < WW) {
                    int4 w = *(const int4*)(tgt_b + gyy * WW + cb);   // 16B-aligned
                    unsigned lo = __byte_perm((unsigned)w.x, (unsigned)w.y, 0x4040);
                    unsigned hi = __byte_perm((unsigned)w.z, (unsigned)w.w, 0x4040);
                    u = __byte_perm(lo, hi, 0x5410);
                }
                s_t[idx] = u;
            }
        }
    }
    __syncthreads();

    // ---- SIMD byte morphology over 12-byte window (uints tx, tx+1, tx+2) ----
    // pixel p's 5-window = bytes (2+p .. 6+p) of the window; center taps = uint tx+1
    unsigned d, t_packed;
    {
        const int u0 = ty * HU + tx;
        unsigned r1a = s_t[u0 + HU],     r1b = s_t[u0 + HU + 1],     r1c = s_t[u0 + HU + 2];
        unsigned r2a = s_t[u0 + 2*HU],   r2b = s_t[u0 + 2*HU + 1],   r2c = s_t[u0 + 2*HU + 2];
        unsigned r3a = s_t[u0 + 3*HU],   r3b = s_t[u0 + 3*HU + 1],   r3c = s_t[u0 + 3*HU + 2];
        unsigned c0  = s_t[u0 + 1];               // row y-2, center col
        unsigned c4  = s_t[u0 + 4*HU + 1];        // row y+2, center col

        // vertical reduce rows 1..3
        unsigned xl = __vmaxs4(__vmaxs4(r1a, r2a), r3a);
        unsigned xm = __vmaxs4(__vmaxs4(r1b, r2b), r3b);
        unsigned xh = __vmaxs4(__vmaxs4(r1c, r2c), r3c);
        unsigned nl = __vminu4(__vminu4(r1a, r2a), r3a);
        unsigned nm = __vminu4(__vminu4(r1b, r2b), r3b);
        unsigned nh = __vminu4(__vminu4(r1c, r2c), r3c);

        // horizontal 5-window: shifted byte vectors s2..s6 (s4 = middle uint)
        unsigned mx = __vmaxs4(
            __vmaxs4(__byte_perm(xl, xm, 0x5432), __byte_perm(xl, xm, 0x6543)),
            __vmaxs4(xm,
            __vmaxs4(__byte_perm(xm, xh, 0x4321), __byte_perm(xm, xh, 0x5432))));
        unsigned mn = __vminu4(
            __vminu4(__byte_perm(nl, nm, 0x5432), __byte_perm(nl, nm, 0x6543)),
            __vminu4(nm,
            __vminu4(__byte_perm(nm, nh, 0x4321), __byte_perm(nm, nh, 0x5432))));

        mx = __vmaxs4(mx, __vmaxs4(c0, c4));
        mn = __vminu4(mn, __vminu4(c0, c4));

        t_packed = r2b;          // 4 target labels (center row, center uint)
        d = mx ^ mn;             // nonzero byte -> boundary pixel
    }

    float sump[CC], inter[CC];
    unsigned cntA = 0, cntB = 0;
#pragma unroll
    for (int c = 0; c < CC; c++) { sump[c] = 0.f; inter[c] = 0.f; }
    float cw_s = 0.f;            // merged: ce*(CE_W + BD_W*w) = ce*(1+2w), w in {1,10}

#pragma unroll
    for (int p = 0; p < 4; p++) {
        const unsigned tp = __byte_perm(t_packed, 0u, 0x4440u | p);
        const unsigned db = __byte_perm(d, 0u, 0x4440u | p);

        // exp WITHOUT max-subtraction: inputs N(0,1), |x| < ~6, no overflow
        float e[CC];
#pragma unroll
        for (int c = 0; c < CC; c++) e[c] = __expf(CP(X[c], p));
        float se = ((e[0] + e[1]) + (e[2] + e[3])) + ((e[4] + e[5]) + (e[6] + e[7]));
        float inv = __fdividef(1.0f, se);

        // target logit via select chain; ce = log(se) - x_t
        float xt = CP(X[0], p);
#pragma unroll
        for (int c = 1; c < CC; c++) xt = (tp == (unsigned)c) ? CP(X[c], p) : xt;
        const float ce = __logf(se) - xt;

#pragma unroll
        for (int c = 0; c < CC; c++) {
            sump[c] = fmaf(e[c], inv, sump[c]);
            if (tp == (unsigned)c) inter[c] = fmaf(e[c], inv, inter[c]);  // predicated FFMA
        }

        cw_s = fmaf(db ? 21.0f : 3.0f, ce, cw_s);

        unsigned inc = 1u << ((tp & 3u) * 8);
        cntA += (tp < 4u) ? inc : 0u;
        cntB += (tp < 4u) ? 0u : inc;
    }

    // ---- block reduction: 3 shuffle levels (lanes 0-3 hold partials) ----
    const int lane = tid & 31;
    const int warp = tid >> 5;
    {
        float q[17];
#pragma unroll
        for (int c = 0; c < CC; c++) { q[c] = sump[c]; q[8 + c] = inter[c]; }
        q[16] = cw_s;
#pragma unroll
        for (int k = 0; k < 17; k++) {
            float v = q[k];
            v += __shfl_down_sync(0xFFFFFFFFu, v, 16);
            v += __shfl_down_sync(0xFFFFFFFFu, v, 8);
            v += __shfl_down_sync(0xFFFFFFFFu, v, 4);
            if (lane < 4) s_red[k][warp * 4 + lane] = v;
        }
        unsigned ua = __reduce_add_sync(0xFFFFFFFFu, cntA);   // REDUX.SUM
        unsigned ub = __reduce_add_sync(0xFFFFFFFFu, cntB);
        if (lane == 0) { s_cnt[0][warp] = ua; s_cnt[1][warp] = ub; }
    }
    __syncthreads();

    if (tid < 17) {
        float s = 0.f;
#pragma unroll
        for (int w = 0; w < 32; w++) s += s_red[tid][w];
        int gi = (tid < 16) ? tid : 24;
        atomicAdd(&g_acc[b][gi], (double)s);
    }
    if (tid >= 32 && tid < 40) {
        int c = tid - 32;
        unsigned s = 0;
#pragma unroll
        for (int w = 0; w < NWARPS; w++)
            s += (s_cnt[c >> 2][w] >> ((c & 3) * 8)) & 0xFFu;
        atomicAdd(&g_acc[b][16 + c], (double)s);
    }

    // ---- last-block finalize ----
    __syncthreads();
    if (tid == 0) {
        __threadfence();
        unsigned r = atomicAdd(&g_ticket, 1u);
        s_last = (r == NBLOCKS - 1);
        s_fin[0] = 0.f; s_fin[1] = 0.f;
    }
    __syncthreads();
    if (!s_last) return;
    __threadfence();

    float dterm = 0.f;
    if (tid < BB * CC) {
        int bb = tid >> 3, cc = tid & 7;
        float it   = (float)g_acc[bb][8 + cc];
        float card = (float)(g_acc[bb][cc] + g_acc[bb][16 + cc]);
        dterm = (2.0f * it + 1e-6f) / (card + 1e-6f);
    }
#pragma unroll
    for (int off = 16; off > 0; off >>= 1)
        dterm += __shfl_down_sync(0xFFFFFFFFu, dterm, off);
    if (lane == 0 && warp < 2) atomicAdd(&s_fin[0], dterm);
    if (tid < BB) atomicAdd(&s_fin[1], (float)g_acc[tid][24]);
    __syncthreads();

    if (tid == 0) {
        const float N = (float)BB * HH * WW;
        float dice = 1.0f - s_fin[0] / (float)(BB * CC);
        out[0] = s_fin[1] / N + 3.0f * dice;
    }
    if (tid < BB * 26) ((double*)g_acc)[tid] = 0.0;
    if (tid == 0) g_ticket = 0u;
}

extern "C" void kernel_launch(void* const* d_in, const int* in_sizes, int n_in,
                              void* d_out, int out_size)
{
    const float* pred   = (const float*)d_in[0];
    const int*   target = (const int*)d_in[1];
    float* out = (float*)d_out;

    dim3 block(BX, BY, 1);
    dim3 grid(WW / TW, HH / TH, BB);
    loss_main_kernel<<<grid, block>>>(pred, target, out);
}

// round 12
// speedup vs baseline: 1.5677x; 1.0444x over previous
#include <cuda_runtime.h>
#include <cuda_bf16.h>

// Fixed shapes
#define BB 8
#define CC 8
#define HH 512
#define WW 1024
#define HWSZ (HH * WW)

// Tiling: 32x8 threads; each thread owns 8 pixels = 2 adjacent rows x 4 cols
#define BX 32
#define BY 8
#define TW (BX * 4)        // tile width 128 px
#define TH 16              // tile height 16 px (2 rows per thread)
#define NWARPS 8
#define NBLOCKS ((WW / TW) * (HH / TH) * BB)   // 2048

#define HROWS (TH + 4)     // 20
#define HU 34              // uints per halo row (136 bytes: cols gx0-4 .. gx0+131)
#define HTOT (HROWS * HU)  // 680 uints

__device__ double g_acc[BB][26];   // zeroed at module load; last block re-zeroes
__device__ unsigned g_ticket;

#define CP(v, p) ((p) == 0 ? (v).x : (p) == 1 ? (v).y : (p) == 2 ? (v).z : (v).w)

__device__ __forceinline__ unsigned hwin_max(unsigned l, unsigned m, unsigned h) {
    return __vmaxs4(__vmaxs4(__byte_perm(l, m, 0x5432), __byte_perm(l, m, 0x6543)),
           __vmaxs4(m, __vmaxs4(__byte_perm(m, h, 0x4321), __byte_perm(m, h, 0x5432))));
}
__device__ __forceinline__ unsigned hwin_min(unsigned l, unsigned m, unsigned h) {
    return __vminu4(__vminu4(__byte_perm(l, m, 0x5432), __byte_perm(l, m, 0x6543)),
           __vminu4(m, __vminu4(__byte_perm(m, h, 0x4321), __byte_perm(m, h, 0x5432))));
}

__global__ __launch_bounds__(256, 4) void loss_main_kernel(
    const float* __restrict__ pred, const int* __restrict__ target,
    float* __restrict__ out)
{
    __shared__ __align__(16) unsigned s_t[HTOT];        // packed byte labels
    __shared__ float s_red[17][33];                     // padded (bank-conflict-free)
    __shared__ unsigned s_cnt[2][16];
    __shared__ float s_fin[2];
    __shared__ int s_last;

    const int b   = blockIdx.z;
    const int gx0 = blockIdx.x * TW;
    const int gy0 = blockIdx.y * TH;
    const int tx  = threadIdx.x;
    const int ty  = threadIdx.y;
    const int tid = ty * BX + tx;

    // ---- HOISTED row-A pred loads: 8 independent LDG.128 first; consumed
    //      after staging + sync + morphology (covers DRAM latency) ----
    const int gy = gy0 + 2 * ty;          // row A; row B = gy+1
    const int gx = gx0 + tx * 4;
    const float* pb = pred + (size_t)b * CC * HWSZ + (size_t)gy * WW + gx;
    float4 X[CC];
#pragma unroll
    for (int c = 0; c < CC; c++) X[c] = __ldcs((const float4*)(pb + (size_t)c * HWSZ));

    // ---- stage target halo as packed bytes: int4 load + PRMT pack ----
    // uint j of halo row covers cols gx0-4+4j .. +3; OOB uint -> 0xFFFFFFFF
    {
        const int* tgt_b = target + b * HWSZ;
#pragma unroll
        for (int k = 0; k < 3; k++) {
            int idx = tid + k * 256;
            if (idx < HTOT) {
                int row = idx / HU;
                int j   = idx - row * HU;
                int gyy = gy0 + row - 2;
                int cb  = gx0 - 4 + 4 * j;
                unsigned u = 0xFFFFFFFFu;
                if (gyy >= 0 && gyy < HH && cb >= 0 && cb < WW) {
                    int4 w = *(const int4*)(tgt_b + gyy * WW + cb);   // 16B-aligned
                    unsigned lo = __byte_perm((unsigned)w.x, (unsigned)w.y, 0x4040);
                    unsigned hi = __byte_perm((unsigned)w.z, (unsigned)w.w, 0x4040);
                    u = __byte_perm(lo, hi, 0x5410);
                }
                s_t[idx] = u;
            }
        }
    }
    __syncthreads();

    // ---- SIMD byte morphology for 2 adjacent rows (shared vertical pair) ----
    // pixel row r=2ty sits at halo row r+2; its window = halo rows r..r+4.
    // Row B (r+1) window = halo rows r+1..r+5. Shared pair: halo rows r+2,r+3.
    unsigned dA, dB, tA, tB;
    {
        const int hb = (2 * ty) * HU + tx;
        unsigned h1a = s_t[hb + HU],     h1b = s_t[hb + HU + 1],     h1c = s_t[hb + HU + 2];
        unsigned h2a = s_t[hb + 2*HU],   h2b = s_t[hb + 2*HU + 1],   h2c = s_t[hb + 2*HU + 2];
        unsigned h3a = s_t[hb + 3*HU],   h3b = s_t[hb + 3*HU + 1],   h3c = s_t[hb + 3*HU + 2];
        unsigned h4a = s_t[hb + 4*HU],   h4b = s_t[hb + 4*HU + 1],   h4c = s_t[hb + 4*HU + 2];
        unsigned c0  = s_t[hb + 1];            // halo row r,   center uint
        unsigned c5  = s_t[hb + 5*HU + 1];     // halo row r+5, center uint

        // shared vertical pair (halo rows r+2, r+3)
        unsigned pxa = __vmaxs4(h2a, h3a), pxb = __vmaxs4(h2b, h3b), pxc = __vmaxs4(h2c, h3c);
        unsigned qna = __vminu4(h2a, h3a), qnb = __vminu4(h2b, h3b), qnc = __vminu4(h2c, h3c);

        // Row A vertical: pair + h1 ; Row B vertical: pair + h4
        unsigned mxA = __vmaxs4(hwin_max(__vmaxs4(pxa, h1a), __vmaxs4(pxb, h1b), __vmaxs4(pxc, h1c)),
                                __vmaxs4(c0, h4b));
        unsigned mnA = __vminu4(hwin_min(__vminu4(qna, h1a), __vminu4(qnb, h1b), __vminu4(qnc, h1c)),
                                __vminu4(c0, h4b));
        unsigned mxB = __vmaxs4(hwin_max(__vmaxs4(pxa, h4a), __vmaxs4(pxb, h4b), __vmaxs4(pxc, h4c)),
                                __vmaxs4(h1b, c5));
        unsigned mnB = __vminu4(hwin_min(__vminu4(qna, h4a), __vminu4(qnb, h4b), __vminu4(qnc, h4c)),
                                __vminu4(h1b, c5));

        tA = h2b;  dA = mxA ^ mnA;             // row A labels / boundary bytes
        tB = h3b;  dB = mxB ^ mnB;             // row B
    }

    float sump[CC], inter[CC];
    unsigned cntA = 0, cntB = 0;               // classes 0-3 / 4-7, 8-bit fields (max 8/thread)
#pragma unroll
    for (int c = 0; c < CC; c++) { sump[c] = 0.f; inter[c] = 0.f; }
    float cw_s = 0.f;                          // ce*(1+2w), w in {1,10} -> 3 or 21

    auto proc_row = [&](unsigned t_packed, unsigned d) {
#pragma unroll
        for (int p = 0; p < 4; p++) {
            const unsigned tp = __byte_perm(t_packed, 0u, 0x4440u | p);
            const unsigned db = __byte_perm(d, 0u, 0x4440u | p);

            // exp WITHOUT max-subtraction: inputs N(0,1), |x| < ~6, no overflow
            float e[CC];
#pragma unroll
            for (int c = 0; c < CC; c++) e[c] = __expf(CP(X[c], p));
            float se = ((e[0] + e[1]) + (e[2] + e[3])) + ((e[4] + e[5]) + (e[6] + e[7]));
            float inv = __fdividef(1.0f, se);

            float xt = CP(X[0], p);
#pragma unroll
            for (int c = 1; c < CC; c++) xt = (tp == (unsigned)c) ? CP(X[c], p) : xt;
            const float ce = __logf(se) - xt;

#pragma unroll
            for (int c = 0; c < CC; c++) {
                sump[c] = fmaf(e[c], inv, sump[c]);
                if (tp == (unsigned)c) inter[c] = fmaf(e[c], inv, inter[c]);
            }

            cw_s = fmaf(db ? 21.0f : 3.0f, ce, cw_s);

            unsigned inc = 1u << ((tp & 3u) * 8);
            cntA += (tp < 4u) ? inc : 0u;
            cntB += (tp < 4u) ? 0u : inc;
        }
    };

    proc_row(tA, dA);                          // row A (X already loaded)

#pragma unroll
    for (int c = 0; c < CC; c++)               // row B loads into same regs
        X[c] = __ldcs((const float4*)(pb + (size_t)c * HWSZ + WW));
    proc_row(tB, dB);

    // ---- block reduction: 3 shuffle levels (lanes 0-3 hold partials) ----
    const int lane = tid & 31;
    const int warp = tid >> 5;
    {
        float q[17];
#pragma unroll
        for (int c = 0; c < CC; c++) { q[c] = sump[c]; q[8 + c] = inter[c]; }
        q[16] = cw_s;
#pragma unroll
        for (int k = 0; k < 17; k++) {
            float v = q[k];
            v += __shfl_down_sync(0xFFFFFFFFu, v, 16);
            v += __shfl_down_sync(0xFFFFFFFFu, v, 8);
            v += __shfl_down_sync(0xFFFFFFFFu, v, 4);
            if (lane < 4) s_red[k][warp * 4 + lane] = v;
        }
        // counts: two 16-lane REDUX halves (8-bit fields, max 8*16=128, no overflow)
        unsigned ua, ub;
        if (lane < 16) {
            ua = __reduce_add_sync(0x0000FFFFu, cntA);
            ub = __reduce_add_sync(0x0000FFFFu, cntB);
        } else {
            ua = __reduce_add_sync(0xFFFF0000u, cntA);
            ub = __reduce_add_sync(0xFFFF0000u, cntB);
        }
        if ((lane & 15) == 0) {
            s_cnt[0][warp * 2 + (lane >> 4)] = ua;
            s_cnt[1][warp * 2 + (lane >> 4)] = ub;
        }
    }
    __syncthreads();

    if (tid < 17) {
        float s = 0.f;
#pragma unroll
        for (int w = 0; w < 32; w++) s += s_red[tid][w];
        int gi = (tid < 16) ? tid : 24;
        atomicAdd(&g_acc[b][gi], (double)s);
    }
    if (tid >= 32 && tid < 40) {
        int c = tid - 32;
        unsigned s = 0;
#pragma unroll
        for (int w = 0; w < 16; w++)
            s += (s_cnt[c >> 2][w] >> ((c & 3) * 8)) & 0xFFu;
        atomicAdd(&g_acc[b][16 + c], (double)s);
    }

    // ---- last-block finalize ----
    __syncthreads();
    if (tid == 0) {
        __threadfence();
        unsigned r = atomicAdd(&g_ticket, 1u);
        s_last = (r == NBLOCKS - 1);
        s_fin[0] = 0.f; s_fin[1] = 0.f;
    }
    __syncthreads();
    if (!s_last) return;
    __threadfence();

    float dterm = 0.f;
    if (tid < BB * CC) {
        int bb = tid >> 3, cc = tid & 7;
        float it   = (float)g_acc[bb][8 + cc];
        float card = (float)(g_acc[bb][cc] + g_acc[bb][16 + cc]);
        dterm = (2.0f * it + 1e-6f) / (card + 1e-6f);
    }
#pragma unroll
    for (int off = 16; off > 0; off >>= 1)
        dterm += __shfl_down_sync(0xFFFFFFFFu, dterm, off);
    if (lane == 0 && warp < 2) atomicAdd(&s_fin[0], dterm);
    if (tid < BB) atomicAdd(&s_fin[1], (float)g_acc[tid][24]);
    __syncthreads();

    if (tid == 0) {
        const float N = (float)BB * HH * WW;
        float dice = 1.0f - s_fin[0] / (float)(BB * CC);
        out[0] = s_fin[1] / N + 3.0f * dice;
    }
    if (tid < BB * 26) ((double*)g_acc)[tid] = 0.0;
    if (tid == 0) g_ticket = 0u;
}

extern "C" void kernel_launch(void* const* d_in, const int* in_sizes, int n_in,
                              void* d_out, int out_size)
{
    const float* pred   = (const float*)d_in[0];
    const int*   target = (const int*)d_in[1];
    float* out = (float*)d_out;

    dim3 block(BX, BY, 1);
    dim3 grid(WW / TW, HH / TH, BB);
    loss_main_kernel<<<grid, block>>>(pred, target, out);
}